// round 15
// baseline (speedup 1.0000x reference)
#include <cuda_runtime.h>

#define Cdim 768
#define CRdim 192
#define Bb 8
#define Nn 1024

// gc accumulator (atomic; zeroed by k_ln each call, after its last use)
__device__ __align__(16) float g_gc[Bb * Cdim];
// other accumulators (zeroed by k_gc's spare blocks each call)
#define S_VB 0
#define S_CA (Bb * Cdim)
#define S_YB (2 * Bb * Cdim)
#define S_H  (3 * Bb * Cdim)
#define S_ACC_N (3 * Bb * Cdim + Bb * CRdim)
__device__ __align__(16) float g_acc[S_ACC_N];

__device__ __forceinline__ float4 ldg128(const float4* p) {
    float4 v;
    asm volatile("ld.global.nc.v4.f32 {%0,%1,%2,%3}, [%4];"
                 : "=f"(v.x), "=f"(v.y), "=f"(v.z), "=f"(v.w) : "l"(p));
    return v;
}

// ───────── K1: gc reduce (blocks 0..511, 16 rows each) + zero g_acc ────────
__global__ void __launch_bounds__(192) k_gc(const float* __restrict__ x) {
    int t = threadIdx.x, g = blockIdx.x;
    if (g < 512) {
        int b = g >> 6;                  // batch
        int chunk = g & 63;              // 16-row chunk
        const float4* p = reinterpret_cast<const float4*>(x)
                        + (size_t)(b * Nn + chunk * 16) * (Cdim / 4) + t;
        float sx = 0.f, sy = 0.f, sz = 0.f, sw = 0.f;
        #pragma unroll
        for (int r = 0; r < 2; r++) {
            float4 v0 = ldg128(p + (r * 8 + 0) * (Cdim / 4));
            float4 v1 = ldg128(p + (r * 8 + 1) * (Cdim / 4));
            float4 v2 = ldg128(p + (r * 8 + 2) * (Cdim / 4));
            float4 v3 = ldg128(p + (r * 8 + 3) * (Cdim / 4));
            float4 v4 = ldg128(p + (r * 8 + 4) * (Cdim / 4));
            float4 v5 = ldg128(p + (r * 8 + 5) * (Cdim / 4));
            float4 v6 = ldg128(p + (r * 8 + 6) * (Cdim / 4));
            float4 v7 = ldg128(p + (r * 8 + 7) * (Cdim / 4));
            sx += ((v0.x + v1.x) + (v2.x + v3.x)) + ((v4.x + v5.x) + (v6.x + v7.x));
            sy += ((v0.y + v1.y) + (v2.y + v3.y)) + ((v4.y + v5.y) + (v6.y + v7.y));
            sz += ((v0.z + v1.z) + (v2.z + v3.z)) + ((v4.z + v5.z) + (v6.z + v7.z));
            sw += ((v0.w + v1.w) + (v2.w + v3.w)) + ((v4.w + v5.w) + (v6.w + v7.w));
        }
        float* gp = &g_gc[b * Cdim + 4 * t];
        const float inv = 1.0f / Nn;
        atomicAdd(gp + 0, sx * inv);
        atomicAdd(gp + 1, sy * inv);
        atomicAdd(gp + 2, sz * inv);
        atomicAdd(gp + 3, sw * inv);
    } else {
        for (int i = (g - 512) * 192 + t; i < S_ACC_N; i += 8 * 192)
            g_acc[i] = 0.f;
    }
}

// ───────── K2: vbar = gc@Wv, h = gc@W1   (atomic k-split) ──────────────────
// 120 blocks × 192 threads. Thread = (quad q8 = t>>3 of 24, k-lane kg = t&7).
__global__ void __launch_bounds__(192) k_gemm1(const float* __restrict__ Wv,
                                               const float* __restrict__ W1) {
    __shared__ float sa[Bb][64];
    int t = threadIdx.x, g = blockIdx.x;
    int q8 = t >> 3, kg = t & 7;
    int ct = g / 12;                // 0..9   (col tile of 24 quads)
    int kt = g % 12;                // 0..11  (k tile of 64)
    int k0 = kt * 64;
    for (int i = t; i < Bb * 64; i += 192) {
        int b = i >> 6, kk = i & 63;
        sa[b][kk] = g_gc[b * Cdim + k0 + kk];
    }
    __syncthreads();
    int Q = ct * 24 + q8;           // 0..239 col-quad
    float acc[Bb][4];
    #pragma unroll
    for (int b = 0; b < Bb; b++) { acc[b][0]=0.f; acc[b][1]=0.f; acc[b][2]=0.f; acc[b][3]=0.f; }
    if (Q < 192) {
        const float4* wp = (const float4*)Wv + (size_t)(k0 + kg * 8) * 192 + Q;
        #pragma unroll
        for (int kk = 0; kk < 8; kk++) {
            float4 w = ldg128(wp + (size_t)kk * 192);
            int ki = kg * 8 + kk;
            #pragma unroll
            for (int b = 0; b < Bb; b++) {
                float a = sa[b][ki];
                acc[b][0] += a * w.x; acc[b][1] += a * w.y;
                acc[b][2] += a * w.z; acc[b][3] += a * w.w;
            }
        }
    } else {
        const float4* wp = (const float4*)W1 + (size_t)(k0 + kg * 8) * 48 + (Q - 192);
        #pragma unroll
        for (int kk = 0; kk < 8; kk++) {
            float4 w = ldg128(wp + (size_t)kk * 48);
            int ki = kg * 8 + kk;
            #pragma unroll
            for (int b = 0; b < Bb; b++) {
                float a = sa[b][ki];
                acc[b][0] += a * w.x; acc[b][1] += a * w.y;
                acc[b][2] += a * w.z; acc[b][3] += a * w.w;
            }
        }
    }
    #pragma unroll
    for (int b = 0; b < Bb; b++)
        #pragma unroll
        for (int j = 0; j < 4; j++) {
            acc[b][j] += __shfl_xor_sync(0xffffffffu, acc[b][j], 1);
            acc[b][j] += __shfl_xor_sync(0xffffffffu, acc[b][j], 2);
            acc[b][j] += __shfl_xor_sync(0xffffffffu, acc[b][j], 4);
        }
    if (kg == 0) {
        if (Q < 192) {
            #pragma unroll
            for (int b = 0; b < Bb; b++)
                #pragma unroll
                for (int j = 0; j < 4; j++)
                    atomicAdd(&g_acc[S_VB + b * Cdim + 4 * Q + j], acc[b][j]);
        } else {
            #pragma unroll
            for (int b = 0; b < Bb; b++)
                #pragma unroll
                for (int j = 0; j < 4; j++)
                    atomicAdd(&g_acc[S_H + b * CRdim + 4 * (Q - 192) + j], acc[b][j]);
        }
    }
}

// ───────── K3: fused gemm2+gemm3 (96 blocks × 192 threads) ────────────────
// Block (ct = g&7, kt = g>>3) computes its OWN 64-col ca slice inline:
//   ca[b, k0:k0+64] = relu(h+b1) @ W2[:, k0:k0+64]   (98K FMA, 48KB of W2)
// then sy = (vbar+bv)*sigmoid(ca+b2) and the Wo GEMM exactly as before.
// Removes a whole kernel launch + serial hop vs separate gemm2/gemm3.
__global__ void __launch_bounds__(192) k_gemm23(const float* __restrict__ Wo,
                                                const float* __restrict__ W2,
                                                const float* __restrict__ bv,
                                                const float* __restrict__ b1,
                                                const float* __restrict__ b2) {
    __shared__ float sh[Bb][CRdim];      // relu(h+b1)       6 KB
    __shared__ float sca[3][Bb][64];     // ca partials      6 KB
    __shared__ float sy[Bb][64];         // gemm3 operand    2 KB
    int t = threadIdx.x, g = blockIdx.x;
    int ct = g & 7;                 // 0..7
    int kt = g >> 3;                // 0..11
    int k0 = kt * 64;

    // load h, add b1, relu (1536 elems over 192 threads)
    for (int i = t; i < Bb * CRdim; i += 192) {
        int b = i / CRdim, m = i % CRdim;
        float v = g_acc[S_H + b * CRdim + m] + b1[m];
        sh[b][m] = v > 0.f ? v : 0.f;
    }
    __syncthreads();

    // ca slice: thread (j = t&63, ms = t>>6) sums m in [ms*64, ms*64+64)
    {
        int j = t & 63, ms = t >> 6;
        float cp[Bb];
        #pragma unroll
        for (int b = 0; b < Bb; b++) cp[b] = 0.f;
        const float* w2p = W2 + (size_t)(ms * 64) * Cdim + k0 + j;
        #pragma unroll 8
        for (int mm = 0; mm < 64; mm++) {
            float w = w2p[(size_t)mm * Cdim];
            #pragma unroll
            for (int b = 0; b < Bb; b++) cp[b] += sh[b][ms * 64 + mm] * w;
        }
        #pragma unroll
        for (int b = 0; b < Bb; b++) sca[ms][b][j] = cp[b];
    }
    __syncthreads();

    // combine partials, sigmoid, multiply by vbar+bv
    for (int i = t; i < Bb * 64; i += 192) {
        int b = i >> 6, jj = i & 63;
        int k = k0 + jj;
        float cp = sca[0][b][jj] + sca[1][b][jj] + sca[2][b][jj] + b2[k];
        float vb = g_acc[S_VB + b * Cdim + k] + bv[k];
        sy[b][jj] = vb * (1.f / (1.f + __expf(-cp)));
    }
    __syncthreads();

    // Wo GEMM (identical to previous k_gemm3 body)
    int q8 = t >> 3, kg = t & 7;
    int Q = ct * 24 + q8;
    float acc[Bb][4];
    #pragma unroll
    for (int b = 0; b < Bb; b++) { acc[b][0]=0.f; acc[b][1]=0.f; acc[b][2]=0.f; acc[b][3]=0.f; }
    const float4* wp = (const float4*)Wo + (size_t)(k0 + kg * 8) * 192 + Q;
    #pragma unroll
    for (int kk = 0; kk < 8; kk++) {
        float4 w = ldg128(wp + (size_t)kk * 192);
        int ki = kg * 8 + kk;
        #pragma unroll
        for (int b = 0; b < Bb; b++) {
            float a = sy[b][ki];
            acc[b][0] += a * w.x; acc[b][1] += a * w.y;
            acc[b][2] += a * w.z; acc[b][3] += a * w.w;
        }
    }
    #pragma unroll
    for (int b = 0; b < Bb; b++)
        #pragma unroll
        for (int j = 0; j < 4; j++) {
            acc[b][j] += __shfl_xor_sync(0xffffffffu, acc[b][j], 1);
            acc[b][j] += __shfl_xor_sync(0xffffffffu, acc[b][j], 2);
            acc[b][j] += __shfl_xor_sync(0xffffffffu, acc[b][j], 4);
        }
    if (kg == 0) {
        #pragma unroll
        for (int b = 0; b < Bb; b++)
            #pragma unroll
            for (int j = 0; j < 4; j++)
                atomicAdd(&g_acc[S_YB + b * Cdim + 4 * Q + j], acc[b][j]);
    }
}

// ───────── K4: fused residual + LN (smem-cached) + gc re-zero ──────────────
// 256 blocks × 256 threads, 32 rows each. Also zeroes g_gc (gc's last
// consumer was k_gemm1, which precedes this kernel) — restores the
// every-call invariant without any extra launch.
__global__ void __launch_bounds__(256) k_ln(const float* __restrict__ x,
                                            const float* __restrict__ bo,
                                            const float* __restrict__ gamma,
                                            const float* __restrict__ beta,
                                            float* __restrict__ out) {
    __shared__ float sw[Cdim], sg[Cdim], sb[Cdim];
    int g = blockIdx.x;                 // 0..255
    int t = threadIdx.x;
    int b = g >> 5;                     // 32 blocks per batch
    if (t < 24) g_gc[g * 24 + t] = 0.f;     // 256*24 = 6144 = Bb*Cdim
    for (int i = t; i < Cdim; i += 256) {
        sw[i] = g_acc[S_YB + b * Cdim + i] + bo[i];
        sg[i] = gamma[i];
        sb[i] = beta[i];
    }
    __syncthreads();
    const float4* wp = reinterpret_cast<const float4*>(sw);
    const float4* gp = reinterpret_cast<const float4*>(sg);
    const float4* ep = reinterpret_cast<const float4*>(sb);
    int w = t >> 5, lane = t & 31;
    int row0 = g * 32;
    #pragma unroll
    for (int rr = 0; rr < 4; rr++) {
        int r = row0 + w + rr * 8;
        const float4* xp = reinterpret_cast<const float4*>(x + (size_t)r * Cdim);
        float4 x0 = ldg128(xp + lane);
        float4 x1 = ldg128(xp + lane + 32);
        float4 x2 = ldg128(xp + lane + 64);
        float4 x3 = ldg128(xp + lane + 96);
        float4 x4 = ldg128(xp + lane + 128);
        float4 x5 = ldg128(xp + lane + 160);
        float4 xv[6] = {x0, x1, x2, x3, x4, x5};
        float4 v[6];
        float s = 0.f, qs = 0.f;
        #pragma unroll
        for (int i = 0; i < 6; i++) {
            int c = lane + 32 * i;
            float4 wv = wp[c];
            v[i].x = xv[i].x + wv.x; v[i].y = xv[i].y + wv.y;
            v[i].z = xv[i].z + wv.z; v[i].w = xv[i].w + wv.w;
            s  += v[i].x + v[i].y + v[i].z + v[i].w;
            qs += v[i].x*v[i].x + v[i].y*v[i].y + v[i].z*v[i].z + v[i].w*v[i].w;
        }
        #pragma unroll
        for (int o = 16; o; o >>= 1) {
            s  += __shfl_xor_sync(0xffffffffu, s, o);
            qs += __shfl_xor_sync(0xffffffffu, qs, o);
        }
        float mean = s * (1.0f / Cdim);
        float var = qs * (1.0f / Cdim) - mean * mean;
        float rstd = rsqrtf(var + 1e-5f);
        float4* op = reinterpret_cast<float4*>(out + (size_t)r * Cdim);
        #pragma unroll
        for (int i = 0; i < 6; i++) {
            int c = lane + 32 * i;
            float4 g4 = gp[c], e4 = ep[c], o4;
            o4.x = (v[i].x - mean) * rstd * g4.x + e4.x;
            o4.y = (v[i].y - mean) * rstd * g4.y + e4.y;
            o4.z = (v[i].z - mean) * rstd * g4.z + e4.z;
            o4.w = (v[i].w - mean) * rstd * g4.w + e4.w;
            op[c] = o4;
        }
    }
}

extern "C" void kernel_launch(void* const* d_in, const int* in_sizes, int n_in,
                              void* d_out, int out_size) {
    const float* x     = (const float*)d_in[0];
    // d_in[1..4] = Wq, bq, Wk, bk — mathematically unused: k is constant over
    // sequence positions, so softmax is exactly uniform and attention output
    // equals mean(v) = gc@Wv + bv, independent of q/k.
    const float* Wv    = (const float*)d_in[5];
    const float* bv    = (const float*)d_in[6];
    const float* W1    = (const float*)d_in[7];
    const float* b1    = (const float*)d_in[8];
    const float* W2    = (const float*)d_in[9];
    const float* b2    = (const float*)d_in[10];
    const float* Wo    = (const float*)d_in[11];
    const float* bo    = (const float*)d_in[12];
    const float* gamma = (const float*)d_in[13];
    const float* beta  = (const float*)d_in[14];
    float* out = (float*)d_out;

    k_gc<<<520, 192>>>(x);
    k_gemm1<<<120, 192>>>(Wv, W1);
    k_gemm23<<<96, 192>>>(Wo, W2, bv, b1, b2);
    k_ln<<<256, 256>>>(x, bo, gamma, beta, out);
}

// round 16
// speedup vs baseline: 1.0943x; 1.0943x over previous
#include <cuda_runtime.h>

#define Cdim 768
#define CRdim 192
#define Bb 8
#define Nn 1024

// gc accumulator (atomic; zeroed by k_gemm2's spare blocks each call)
__device__ __align__(16) float g_gc[Bb * Cdim];
// other accumulators (zeroed by k_gc's spare blocks each call)
#define S_VB 0
#define S_CA (Bb * Cdim)
#define S_YB (2 * Bb * Cdim)
#define S_H  (3 * Bb * Cdim)
#define S_ACC_N (3 * Bb * Cdim + Bb * CRdim)
__device__ __align__(16) float g_acc[S_ACC_N];

__device__ __forceinline__ float4 ldg128(const float4* p) {
    float4 v;
    asm volatile("ld.global.nc.v4.f32 {%0,%1,%2,%3}, [%4];"
                 : "=f"(v.x), "=f"(v.y), "=f"(v.z), "=f"(v.w) : "l"(p));
    return v;
}

// ───────── K1: gc reduce (blocks 0..511, 16 rows each) + zero g_acc ────────
__global__ void __launch_bounds__(192) k_gc(const float* __restrict__ x) {
    int t = threadIdx.x, g = blockIdx.x;
    if (g < 512) {
        int b = g >> 6;                  // batch
        int chunk = g & 63;              // 16-row chunk
        const float4* p = reinterpret_cast<const float4*>(x)
                        + (size_t)(b * Nn + chunk * 16) * (Cdim / 4) + t;
        float sx = 0.f, sy = 0.f, sz = 0.f, sw = 0.f;
        #pragma unroll
        for (int r = 0; r < 2; r++) {
            float4 v0 = ldg128(p + (r * 8 + 0) * (Cdim / 4));
            float4 v1 = ldg128(p + (r * 8 + 1) * (Cdim / 4));
            float4 v2 = ldg128(p + (r * 8 + 2) * (Cdim / 4));
            float4 v3 = ldg128(p + (r * 8 + 3) * (Cdim / 4));
            float4 v4 = ldg128(p + (r * 8 + 4) * (Cdim / 4));
            float4 v5 = ldg128(p + (r * 8 + 5) * (Cdim / 4));
            float4 v6 = ldg128(p + (r * 8 + 6) * (Cdim / 4));
            float4 v7 = ldg128(p + (r * 8 + 7) * (Cdim / 4));
            sx += ((v0.x + v1.x) + (v2.x + v3.x)) + ((v4.x + v5.x) + (v6.x + v7.x));
            sy += ((v0.y + v1.y) + (v2.y + v3.y)) + ((v4.y + v5.y) + (v6.y + v7.y));
            sz += ((v0.z + v1.z) + (v2.z + v3.z)) + ((v4.z + v5.z) + (v6.z + v7.z));
            sw += ((v0.w + v1.w) + (v2.w + v3.w)) + ((v4.w + v5.w) + (v6.w + v7.w));
        }
        float* gp = &g_gc[b * Cdim + 4 * t];
        const float inv = 1.0f / Nn;
        atomicAdd(gp + 0, sx * inv);
        atomicAdd(gp + 1, sy * inv);
        atomicAdd(gp + 2, sz * inv);
        atomicAdd(gp + 3, sw * inv);
    } else {
        for (int i = (g - 512) * 192 + t; i < S_ACC_N; i += 8 * 192)
            g_acc[i] = 0.f;
    }
}

// ───────── K2: vbar = gc@Wv, h = gc@W1   (atomic k-split) ──────────────────
// 120 blocks × 192 threads. Thread = (quad q8 = t>>3 of 24, k-lane kg = t&7).
__global__ void __launch_bounds__(192) k_gemm1(const float* __restrict__ Wv,
                                               const float* __restrict__ W1) {
    __shared__ float sa[Bb][64];
    int t = threadIdx.x, g = blockIdx.x;
    int q8 = t >> 3, kg = t & 7;
    int ct = g / 12;                // 0..9   (col tile of 24 quads)
    int kt = g % 12;                // 0..11  (k tile of 64)
    int k0 = kt * 64;
    for (int i = t; i < Bb * 64; i += 192) {
        int b = i >> 6, kk = i & 63;
        sa[b][kk] = g_gc[b * Cdim + k0 + kk];
    }
    __syncthreads();
    int Q = ct * 24 + q8;           // 0..239 col-quad
    float acc[Bb][4];
    #pragma unroll
    for (int b = 0; b < Bb; b++) { acc[b][0]=0.f; acc[b][1]=0.f; acc[b][2]=0.f; acc[b][3]=0.f; }
    if (Q < 192) {
        const float4* wp = (const float4*)Wv + (size_t)(k0 + kg * 8) * 192 + Q;
        #pragma unroll
        for (int kk = 0; kk < 8; kk++) {
            float4 w = ldg128(wp + (size_t)kk * 192);
            int ki = kg * 8 + kk;
            #pragma unroll
            for (int b = 0; b < Bb; b++) {
                float a = sa[b][ki];
                acc[b][0] += a * w.x; acc[b][1] += a * w.y;
                acc[b][2] += a * w.z; acc[b][3] += a * w.w;
            }
        }
    } else {
        const float4* wp = (const float4*)W1 + (size_t)(k0 + kg * 8) * 48 + (Q - 192);
        #pragma unroll
        for (int kk = 0; kk < 8; kk++) {
            float4 w = ldg128(wp + (size_t)kk * 48);
            int ki = kg * 8 + kk;
            #pragma unroll
            for (int b = 0; b < Bb; b++) {
                float a = sa[b][ki];
                acc[b][0] += a * w.x; acc[b][1] += a * w.y;
                acc[b][2] += a * w.z; acc[b][3] += a * w.w;
            }
        }
    }
    #pragma unroll
    for (int b = 0; b < Bb; b++)
        #pragma unroll
        for (int j = 0; j < 4; j++) {
            acc[b][j] += __shfl_xor_sync(0xffffffffu, acc[b][j], 1);
            acc[b][j] += __shfl_xor_sync(0xffffffffu, acc[b][j], 2);
            acc[b][j] += __shfl_xor_sync(0xffffffffu, acc[b][j], 4);
        }
    if (kg == 0) {
        if (Q < 192) {
            #pragma unroll
            for (int b = 0; b < Bb; b++)
                #pragma unroll
                for (int j = 0; j < 4; j++)
                    atomicAdd(&g_acc[S_VB + b * Cdim + 4 * Q + j], acc[b][j]);
        } else {
            #pragma unroll
            for (int b = 0; b < Bb; b++)
                #pragma unroll
                for (int j = 0; j < 4; j++)
                    atomicAdd(&g_acc[S_H + b * CRdim + 4 * (Q - 192) + j], acc[b][j]);
        }
    }
}

// ───────── K3: ca_pre = relu(h+b1)@W2 (blocks 0..23) + gc re-zero (24..47) ─
__global__ void __launch_bounds__(192) k_gemm2(const float* __restrict__ W2,
                                               const float* __restrict__ b1) {
    __shared__ float sa[Bb][64];
    int t = threadIdx.x, g = blockIdx.x;
    int q8 = t >> 3, kg = t & 7;
    if (g < 24) {
        int ct = g & 7;                 // 0..7 (24-quad tile of 192)
        int kt = g >> 3;                // 0..2 (k tile of 64 over K=192)
        int k0 = kt * 64;
        for (int i = t; i < Bb * 64; i += 192) {
            int b = i >> 6, kk = i & 63;
            float v = g_acc[S_H + b * CRdim + k0 + kk] + b1[k0 + kk];
            sa[b][kk] = v > 0.f ? v : 0.f;
        }
        __syncthreads();
        int Q = ct * 24 + q8;
        float acc[Bb][4];
        #pragma unroll
        for (int b = 0; b < Bb; b++) { acc[b][0]=0.f; acc[b][1]=0.f; acc[b][2]=0.f; acc[b][3]=0.f; }
        const float4* wp = (const float4*)W2 + (size_t)(k0 + kg * 8) * 192 + Q;
        #pragma unroll
        for (int kk = 0; kk < 8; kk++) {
            float4 w = ldg128(wp + (size_t)kk * 192);
            int ki = kg * 8 + kk;
            #pragma unroll
            for (int b = 0; b < Bb; b++) {
                float a = sa[b][ki];
                acc[b][0] += a * w.x; acc[b][1] += a * w.y;
                acc[b][2] += a * w.z; acc[b][3] += a * w.w;
            }
        }
        #pragma unroll
        for (int b = 0; b < Bb; b++)
            #pragma unroll
            for (int j = 0; j < 4; j++) {
                acc[b][j] += __shfl_xor_sync(0xffffffffu, acc[b][j], 1);
                acc[b][j] += __shfl_xor_sync(0xffffffffu, acc[b][j], 2);
                acc[b][j] += __shfl_xor_sync(0xffffffffu, acc[b][j], 4);
            }
        if (kg == 0) {
            #pragma unroll
            for (int b = 0; b < Bb; b++)
                #pragma unroll
                for (int j = 0; j < 4; j++)
                    atomicAdd(&g_acc[S_CA + b * Cdim + 4 * Q + j], acc[b][j]);
        }
    } else {
        // gc fully consumed by k_gemm1 (previous kernel); zero for next call.
        for (int i = (g - 24) * 192 + t; i < Bb * Cdim; i += 24 * 192)
            g_gc[i] = 0.f;
    }
}

// ───────── K4: ybar = ((vbar+bv)*sigmoid(ca+b2))@Wo  (96 blocks) ───────────
__global__ void __launch_bounds__(192) k_gemm3(const float* __restrict__ Wo,
                                               const float* __restrict__ bv,
                                               const float* __restrict__ b2) {
    __shared__ float sa[Bb][64];
    int t = threadIdx.x, g = blockIdx.x;
    int q8 = t >> 3, kg = t & 7;
    int ct = g & 7;                 // 0..7
    int kt = g >> 3;                // 0..11
    int k0 = kt * 64;
    for (int i = t; i < Bb * 64; i += 192) {
        int b = i >> 6, kk = i & 63;
        int k = k0 + kk;
        float vb = g_acc[S_VB + b * Cdim + k] + bv[k];
        float cp = g_acc[S_CA + b * Cdim + k] + b2[k];
        sa[b][kk] = vb * (1.f / (1.f + __expf(-cp)));
    }
    __syncthreads();
    int Q = ct * 24 + q8;
    float acc[Bb][4];
    #pragma unroll
    for (int b = 0; b < Bb; b++) { acc[b][0]=0.f; acc[b][1]=0.f; acc[b][2]=0.f; acc[b][3]=0.f; }
    const float4* wp = (const float4*)Wo + (size_t)(k0 + kg * 8) * 192 + Q;
    #pragma unroll
    for (int kk = 0; kk < 8; kk++) {
        float4 w = ldg128(wp + (size_t)kk * 192);
        int ki = kg * 8 + kk;
        #pragma unroll
        for (int b = 0; b < Bb; b++) {
            float a = sa[b][ki];
            acc[b][0] += a * w.x; acc[b][1] += a * w.y;
            acc[b][2] += a * w.z; acc[b][3] += a * w.w;
        }
    }
    #pragma unroll
    for (int b = 0; b < Bb; b++)
        #pragma unroll
        for (int j = 0; j < 4; j++) {
            acc[b][j] += __shfl_xor_sync(0xffffffffu, acc[b][j], 1);
            acc[b][j] += __shfl_xor_sync(0xffffffffu, acc[b][j], 2);
            acc[b][j] += __shfl_xor_sync(0xffffffffu, acc[b][j], 4);
        }
    if (kg == 0) {
        #pragma unroll
        for (int b = 0; b < Bb; b++)
            #pragma unroll
            for (int j = 0; j < 4; j++)
                atomicAdd(&g_acc[S_YB + b * Cdim + 4 * Q + j], acc[b][j]);
    }
}

// ───────── K5: fused residual + LN — register-lean for occupancy ───────────
// 512 blocks × 256 threads, 16 rows each. Row loop NOT unrolled
// (#pragma unroll 1): only one row's 24 load-regs live at a time, so regs
// stay ~64 → 3-4 blocks/SM instead of 1 (the regs=136/occ=12% bug).
__global__ void __launch_bounds__(256) k_ln(const float* __restrict__ x,
                                            const float* __restrict__ bo,
                                            const float* __restrict__ gamma,
                                            const float* __restrict__ beta,
                                            float* __restrict__ out) {
    __shared__ float sw[Cdim], sg[Cdim], sb[Cdim];
    int g = blockIdx.x;                 // 0..511
    int t = threadIdx.x;
    int b = g >> 6;                     // 64 blocks per batch
    for (int i = t; i < Cdim; i += 256) {
        sw[i] = g_acc[S_YB + b * Cdim + i] + bo[i];
        sg[i] = gamma[i];
        sb[i] = beta[i];
    }
    __syncthreads();
    const float4* wp = reinterpret_cast<const float4*>(sw);
    const float4* gp = reinterpret_cast<const float4*>(sg);
    const float4* ep = reinterpret_cast<const float4*>(sb);
    int w = t >> 5, lane = t & 31;
    int row0 = g * 16;
    #pragma unroll 1
    for (int rr = 0; rr < 2; rr++) {
        int r = row0 + w + rr * 8;
        const float4* xp = reinterpret_cast<const float4*>(x + (size_t)r * Cdim);
        float4 x0 = ldg128(xp + lane);
        float4 x1 = ldg128(xp + lane + 32);
        float4 x2 = ldg128(xp + lane + 64);
        float4 x3 = ldg128(xp + lane + 96);
        float4 x4 = ldg128(xp + lane + 128);
        float4 x5 = ldg128(xp + lane + 160);
        float4 xv[6] = {x0, x1, x2, x3, x4, x5};
        float s = 0.f, qs = 0.f;
        #pragma unroll
        for (int i = 0; i < 6; i++) {
            int c = lane + 32 * i;
            float4 wv = wp[c];
            xv[i].x += wv.x; xv[i].y += wv.y; xv[i].z += wv.z; xv[i].w += wv.w;
            s  += xv[i].x + xv[i].y + xv[i].z + xv[i].w;
            qs += xv[i].x*xv[i].x + xv[i].y*xv[i].y + xv[i].z*xv[i].z + xv[i].w*xv[i].w;
        }
        #pragma unroll
        for (int o = 16; o; o >>= 1) {
            s  += __shfl_xor_sync(0xffffffffu, s, o);
            qs += __shfl_xor_sync(0xffffffffu, qs, o);
        }
        float mean = s * (1.0f / Cdim);
        float var = qs * (1.0f / Cdim) - mean * mean;
        float rstd = rsqrtf(var + 1e-5f);
        float4* op = reinterpret_cast<float4*>(out + (size_t)r * Cdim);
        #pragma unroll
        for (int i = 0; i < 6; i++) {
            int c = lane + 32 * i;
            float4 g4 = gp[c], e4 = ep[c], o4;
            o4.x = (xv[i].x - mean) * rstd * g4.x + e4.x;
            o4.y = (xv[i].y - mean) * rstd * g4.y + e4.y;
            o4.z = (xv[i].z - mean) * rstd * g4.z + e4.z;
            o4.w = (xv[i].w - mean) * rstd * g4.w + e4.w;
            op[c] = o4;
        }
    }
}

extern "C" void kernel_launch(void* const* d_in, const int* in_sizes, int n_in,
                              void* d_out, int out_size) {
    const float* x     = (const float*)d_in[0];
    // d_in[1..4] = Wq, bq, Wk, bk — mathematically unused: k is constant over
    // sequence positions, so softmax is exactly uniform and attention output
    // equals mean(v) = gc@Wv + bv, independent of q/k.
    const float* Wv    = (const float*)d_in[5];
    const float* bv    = (const float*)d_in[6];
    const float* W1    = (const float*)d_in[7];
    const float* b1    = (const float*)d_in[8];
    const float* W2    = (const float*)d_in[9];
    const float* b2    = (const float*)d_in[10];
    const float* Wo    = (const float*)d_in[11];
    const float* bo    = (const float*)d_in[12];
    const float* gamma = (const float*)d_in[13];
    const float* beta  = (const float*)d_in[14];
    float* out = (float*)d_out;

    k_gc<<<520, 192>>>(x);
    k_gemm1<<<120, 192>>>(Wv, W1);
    k_gemm2<<<48, 192>>>(W2, b1);     // 24 GEMM blocks + 24 gc-zero blocks
    k_gemm3<<<96, 192>>>(Wo, bv, b2);
    k_ln<<<512, 256>>>(x, bo, gamma, beta, out);
}

// round 17
// speedup vs baseline: 1.0956x; 1.0011x over previous
#include <cuda_runtime.h>

#define Cdim 768
#define CRdim 192
#define Bb 8
#define Nn 1024

// gc accumulator (atomic; zeroed by k_gemm2's spare blocks each call)
__device__ __align__(16) float g_gc[Bb * Cdim];
// other accumulators (zeroed by k_gc's spare blocks each call)
#define S_VB 0
#define S_CA (Bb * Cdim)
#define S_YB (2 * Bb * Cdim)
#define S_H  (3 * Bb * Cdim)
#define S_ACC_N (3 * Bb * Cdim + Bb * CRdim)
__device__ __align__(16) float g_acc[S_ACC_N];

__device__ __forceinline__ float4 ldg128(const float4* p) {
    float4 v;
    asm volatile("ld.global.nc.v4.f32 {%0,%1,%2,%3}, [%4];"
                 : "=f"(v.x), "=f"(v.y), "=f"(v.z), "=f"(v.w) : "l"(p));
    return v;
}

// ───────── K1: gc reduce (blocks 0..511, 16 rows each) + zero g_acc ────────
__global__ void __launch_bounds__(192) k_gc(const float* __restrict__ x) {
    cudaTriggerProgrammaticLaunchCompletion();   // let k_gemm1 launch early
    int t = threadIdx.x, g = blockIdx.x;
    if (g < 512) {
        int b = g >> 6;                  // batch
        int chunk = g & 63;              // 16-row chunk
        const float4* p = reinterpret_cast<const float4*>(x)
                        + (size_t)(b * Nn + chunk * 16) * (Cdim / 4) + t;
        float sx = 0.f, sy = 0.f, sz = 0.f, sw = 0.f;
        #pragma unroll
        for (int r = 0; r < 2; r++) {
            float4 v0 = ldg128(p + (r * 8 + 0) * (Cdim / 4));
            float4 v1 = ldg128(p + (r * 8 + 1) * (Cdim / 4));
            float4 v2 = ldg128(p + (r * 8 + 2) * (Cdim / 4));
            float4 v3 = ldg128(p + (r * 8 + 3) * (Cdim / 4));
            float4 v4 = ldg128(p + (r * 8 + 4) * (Cdim / 4));
            float4 v5 = ldg128(p + (r * 8 + 5) * (Cdim / 4));
            float4 v6 = ldg128(p + (r * 8 + 6) * (Cdim / 4));
            float4 v7 = ldg128(p + (r * 8 + 7) * (Cdim / 4));
            sx += ((v0.x + v1.x) + (v2.x + v3.x)) + ((v4.x + v5.x) + (v6.x + v7.x));
            sy += ((v0.y + v1.y) + (v2.y + v3.y)) + ((v4.y + v5.y) + (v6.y + v7.y));
            sz += ((v0.z + v1.z) + (v2.z + v3.z)) + ((v4.z + v5.z) + (v6.z + v7.z));
            sw += ((v0.w + v1.w) + (v2.w + v3.w)) + ((v4.w + v5.w) + (v6.w + v7.w));
        }
        float* gp = &g_gc[b * Cdim + 4 * t];
        const float inv = 1.0f / Nn;
        atomicAdd(gp + 0, sx * inv);
        atomicAdd(gp + 1, sy * inv);
        atomicAdd(gp + 2, sz * inv);
        atomicAdd(gp + 3, sw * inv);
    } else {
        for (int i = (g - 512) * 192 + t; i < S_ACC_N; i += 8 * 192)
            g_acc[i] = 0.f;
    }
}

// ───────── K2: vbar = gc@Wv, h = gc@W1   (atomic k-split, PDL) ─────────────
// Weight prefetch happens BEFORE cudaGridDependencySynchronize() → overlaps
// with k_gc's execution tail.
__global__ void __launch_bounds__(192) k_gemm1(const float* __restrict__ Wv,
                                               const float* __restrict__ W1) {
    cudaTriggerProgrammaticLaunchCompletion();
    __shared__ float sa[Bb][64];
    int t = threadIdx.x, g = blockIdx.x;
    int q8 = t >> 3, kg = t & 7;
    int ct = g / 12;                // 0..9   (col tile of 24 quads)
    int kt = g % 12;                // 0..11  (k tile of 64)
    int k0 = kt * 64;
    int Q = ct * 24 + q8;           // 0..239 col-quad

    // prefetch weights (independent of k_gc) BEFORE the dependency sync
    float4 w[8];
    if (Q < 192) {
        const float4* wp = (const float4*)Wv + (size_t)(k0 + kg * 8) * 192 + Q;
        #pragma unroll
        for (int kk = 0; kk < 8; kk++) w[kk] = ldg128(wp + (size_t)kk * 192);
    } else {
        const float4* wp = (const float4*)W1 + (size_t)(k0 + kg * 8) * 48 + (Q - 192);
        #pragma unroll
        for (int kk = 0; kk < 8; kk++) w[kk] = ldg128(wp + (size_t)kk * 48);
    }

    cudaGridDependencySynchronize();   // wait for k_gc (gc + zeroed g_acc)

    for (int i = t; i < Bb * 64; i += 192) {
        int b = i >> 6, kk = i & 63;
        sa[b][kk] = g_gc[b * Cdim + k0 + kk];
    }
    __syncthreads();
    float acc[Bb][4];
    #pragma unroll
    for (int b = 0; b < Bb; b++) { acc[b][0]=0.f; acc[b][1]=0.f; acc[b][2]=0.f; acc[b][3]=0.f; }
    #pragma unroll
    for (int kk = 0; kk < 8; kk++) {
        int ki = kg * 8 + kk;
        #pragma unroll
        for (int b = 0; b < Bb; b++) {
            float a = sa[b][ki];
            acc[b][0] += a * w[kk].x; acc[b][1] += a * w[kk].y;
            acc[b][2] += a * w[kk].z; acc[b][3] += a * w[kk].w;
        }
    }
    #pragma unroll
    for (int b = 0; b < Bb; b++)
        #pragma unroll
        for (int j = 0; j < 4; j++) {
            acc[b][j] += __shfl_xor_sync(0xffffffffu, acc[b][j], 1);
            acc[b][j] += __shfl_xor_sync(0xffffffffu, acc[b][j], 2);
            acc[b][j] += __shfl_xor_sync(0xffffffffu, acc[b][j], 4);
        }
    if (kg == 0) {
        if (Q < 192) {
            #pragma unroll
            for (int b = 0; b < Bb; b++)
                #pragma unroll
                for (int j = 0; j < 4; j++)
                    atomicAdd(&g_acc[S_VB + b * Cdim + 4 * Q + j], acc[b][j]);
        } else {
            #pragma unroll
            for (int b = 0; b < Bb; b++)
                #pragma unroll
                for (int j = 0; j < 4; j++)
                    atomicAdd(&g_acc[S_H + b * CRdim + 4 * (Q - 192) + j], acc[b][j]);
        }
    }
}

// ───────── K3: ca_pre = relu(h+b1)@W2 (0..23) + gc re-zero (24..47), PDL ───
__global__ void __launch_bounds__(192) k_gemm2(const float* __restrict__ W2,
                                               const float* __restrict__ b1) {
    cudaTriggerProgrammaticLaunchCompletion();
    __shared__ float sa[Bb][64];
    int t = threadIdx.x, g = blockIdx.x;
    int q8 = t >> 3, kg = t & 7;
    if (g < 24) {
        int ct = g & 7;                 // 0..7 (24-quad tile of 192)
        int kt = g >> 3;                // 0..2 (k tile of 64 over K=192)
        int k0 = kt * 64;
        int Q = ct * 24 + q8;
        // prefetch W2 before sync (independent of gemm1)
        float4 w[8];
        const float4* wp = (const float4*)W2 + (size_t)(k0 + kg * 8) * 192 + Q;
        #pragma unroll
        for (int kk = 0; kk < 8; kk++) w[kk] = ldg128(wp + (size_t)kk * 192);

        cudaGridDependencySynchronize();   // wait for gemm1's h

        for (int i = t; i < Bb * 64; i += 192) {
            int b = i >> 6, kk = i & 63;
            float v = g_acc[S_H + b * CRdim + k0 + kk] + b1[k0 + kk];
            sa[b][kk] = v > 0.f ? v : 0.f;
        }
        __syncthreads();
        float acc[Bb][4];
        #pragma unroll
        for (int b = 0; b < Bb; b++) { acc[b][0]=0.f; acc[b][1]=0.f; acc[b][2]=0.f; acc[b][3]=0.f; }
        #pragma unroll
        for (int kk = 0; kk < 8; kk++) {
            int ki = kg * 8 + kk;
            #pragma unroll
            for (int b = 0; b < Bb; b++) {
                float a = sa[b][ki];
                acc[b][0] += a * w[kk].x; acc[b][1] += a * w[kk].y;
                acc[b][2] += a * w[kk].z; acc[b][3] += a * w[kk].w;
            }
        }
        #pragma unroll
        for (int b = 0; b < Bb; b++)
            #pragma unroll
            for (int j = 0; j < 4; j++) {
                acc[b][j] += __shfl_xor_sync(0xffffffffu, acc[b][j], 1);
                acc[b][j] += __shfl_xor_sync(0xffffffffu, acc[b][j], 2);
                acc[b][j] += __shfl_xor_sync(0xffffffffu, acc[b][j], 4);
            }
        if (kg == 0) {
            #pragma unroll
            for (int b = 0; b < Bb; b++)
                #pragma unroll
                for (int j = 0; j < 4; j++)
                    atomicAdd(&g_acc[S_CA + b * Cdim + 4 * Q + j], acc[b][j]);
        }
    } else {
        // MUST wait: gemm1 still reads gc until it completes.
        cudaGridDependencySynchronize();
        for (int i = (g - 24) * 192 + t; i < Bb * Cdim; i += 24 * 192)
            g_gc[i] = 0.f;
    }
}

// ───────── K4: ybar = ((vbar+bv)*sigmoid(ca+b2))@Wo  (96 blocks, PDL) ──────
__global__ void __launch_bounds__(192) k_gemm3(const float* __restrict__ Wo,
                                               const float* __restrict__ bv,
                                               const float* __restrict__ b2) {
    cudaTriggerProgrammaticLaunchCompletion();
    __shared__ float sa[Bb][64];
    int t = threadIdx.x, g = blockIdx.x;
    int q8 = t >> 3, kg = t & 7;
    int ct = g & 7;                 // 0..7
    int kt = g >> 3;                // 0..11
    int k0 = kt * 64;
    int Q = ct * 24 + q8;
    // prefetch Wo before sync (independent of gemm2)
    float4 w[8];
    const float4* wp = (const float4*)Wo + (size_t)(k0 + kg * 8) * 192 + Q;
    #pragma unroll
    for (int kk = 0; kk < 8; kk++) w[kk] = ldg128(wp + (size_t)kk * 192);

    cudaGridDependencySynchronize();   // wait for gemm2's ca

    for (int i = t; i < Bb * 64; i += 192) {
        int b = i >> 6, kk = i & 63;
        int k = k0 + kk;
        float vb = g_acc[S_VB + b * Cdim + k] + bv[k];
        float cp = g_acc[S_CA + b * Cdim + k] + b2[k];
        sa[b][kk] = vb * (1.f / (1.f + __expf(-cp)));
    }
    __syncthreads();
    float acc[Bb][4];
    #pragma unroll
    for (int b = 0; b < Bb; b++) { acc[b][0]=0.f; acc[b][1]=0.f; acc[b][2]=0.f; acc[b][3]=0.f; }
    #pragma unroll
    for (int kk = 0; kk < 8; kk++) {
        int ki = kg * 8 + kk;
        #pragma unroll
        for (int b = 0; b < Bb; b++) {
            float a = sa[b][ki];
            acc[b][0] += a * w[kk].x; acc[b][1] += a * w[kk].y;
            acc[b][2] += a * w[kk].z; acc[b][3] += a * w[kk].w;
        }
    }
    #pragma unroll
    for (int b = 0; b < Bb; b++)
        #pragma unroll
        for (int j = 0; j < 4; j++) {
            acc[b][j] += __shfl_xor_sync(0xffffffffu, acc[b][j], 1);
            acc[b][j] += __shfl_xor_sync(0xffffffffu, acc[b][j], 2);
            acc[b][j] += __shfl_xor_sync(0xffffffffu, acc[b][j], 4);
        }
    if (kg == 0) {
        #pragma unroll
        for (int b = 0; b < Bb; b++)
            #pragma unroll
            for (int j = 0; j < 4; j++)
                atomicAdd(&g_acc[S_YB + b * Cdim + 4 * Q + j], acc[b][j]);
    }
}

// ───────── K5: fused residual + LN — register-lean, PDL ────────────────────
// 512 blocks × 256 threads, 16 rows each; row loop kept rolled so regs stay
// low (occupancy fix from R16). gamma/beta smem fill happens pre-sync.
__global__ void __launch_bounds__(256) k_ln(const float* __restrict__ x,
                                            const float* __restrict__ bo,
                                            const float* __restrict__ gamma,
                                            const float* __restrict__ beta,
                                            float* __restrict__ out) {
    __shared__ float sw[Cdim], sg[Cdim], sb[Cdim];
    int g = blockIdx.x;                 // 0..511
    int t = threadIdx.x;
    int b = g >> 6;                     // 64 blocks per batch
    // producer-independent fills first
    for (int i = t; i < Cdim; i += 256) {
        sg[i] = gamma[i];
        sb[i] = beta[i];
    }
    cudaGridDependencySynchronize();    // wait for gemm3's ybar
    for (int i = t; i < Cdim; i += 256)
        sw[i] = g_acc[S_YB + b * Cdim + i] + bo[i];
    __syncthreads();
    const float4* wp = reinterpret_cast<const float4*>(sw);
    const float4* gp = reinterpret_cast<const float4*>(sg);
    const float4* ep = reinterpret_cast<const float4*>(sb);
    int w = t >> 5, lane = t & 31;
    int row0 = g * 16;
    #pragma unroll 1
    for (int rr = 0; rr < 2; rr++) {
        int r = row0 + w + rr * 8;
        const float4* xp = reinterpret_cast<const float4*>(x + (size_t)r * Cdim);
        float4 x0 = ldg128(xp + lane);
        float4 x1 = ldg128(xp + lane + 32);
        float4 x2 = ldg128(xp + lane + 64);
        float4 x3 = ldg128(xp + lane + 96);
        float4 x4 = ldg128(xp + lane + 128);
        float4 x5 = ldg128(xp + lane + 160);
        float4 xv[6] = {x0, x1, x2, x3, x4, x5};
        float s = 0.f, qs = 0.f;
        #pragma unroll
        for (int i = 0; i < 6; i++) {
            int c = lane + 32 * i;
            float4 wv = wp[c];
            xv[i].x += wv.x; xv[i].y += wv.y; xv[i].z += wv.z; xv[i].w += wv.w;
            s  += xv[i].x + xv[i].y + xv[i].z + xv[i].w;
            qs += xv[i].x*xv[i].x + xv[i].y*xv[i].y + xv[i].z*xv[i].z + xv[i].w*xv[i].w;
        }
        #pragma unroll
        for (int o = 16; o; o >>= 1) {
            s  += __shfl_xor_sync(0xffffffffu, s, o);
            qs += __shfl_xor_sync(0xffffffffu, qs, o);
        }
        float mean = s * (1.0f / Cdim);
        float var = qs * (1.0f / Cdim) - mean * mean;
        float rstd = rsqrtf(var + 1e-5f);
        float4* op = reinterpret_cast<float4*>(out + (size_t)r * Cdim);
        #pragma unroll
        for (int i = 0; i < 6; i++) {
            int c = lane + 32 * i;
            float4 g4 = gp[c], e4 = ep[c], o4;
            o4.x = (xv[i].x - mean) * rstd * g4.x + e4.x;
            o4.y = (xv[i].y - mean) * rstd * g4.y + e4.y;
            o4.z = (xv[i].z - mean) * rstd * g4.z + e4.z;
            o4.w = (xv[i].w - mean) * rstd * g4.w + e4.w;
            op[c] = o4;
        }
    }
}

// Helper: launch with Programmatic Stream Serialization (PDL).
template <typename... Args>
static void launch_pdl(void (*kern)(Args...), dim3 grid, dim3 block,
                       Args... args) {
    cudaLaunchConfig_t cfg = {};
    cfg.gridDim = grid;
    cfg.blockDim = block;
    cfg.dynamicSmemBytes = 0;
    cfg.stream = 0;
    cudaLaunchAttribute attr[1];
    attr[0].id = cudaLaunchAttributeProgrammaticStreamSerialization;
    attr[0].val.programmaticStreamSerializationAllowed = 1;
    cfg.attrs = attr;
    cfg.numAttrs = 1;
    cudaLaunchKernelEx(&cfg, kern, args...);
}

extern "C" void kernel_launch(void* const* d_in, const int* in_sizes, int n_in,
                              void* d_out, int out_size) {
    const float* x     = (const float*)d_in[0];
    // d_in[1..4] = Wq, bq, Wk, bk — mathematically unused: k is constant over
    // sequence positions, so softmax is exactly uniform and attention output
    // equals mean(v) = gc@Wv + bv, independent of q/k.
    const float* Wv    = (const float*)d_in[5];
    const float* bv    = (const float*)d_in[6];
    const float* W1    = (const float*)d_in[7];
    const float* b1    = (const float*)d_in[8];
    const float* W2    = (const float*)d_in[9];
    const float* b2    = (const float*)d_in[10];
    const float* Wo    = (const float*)d_in[11];
    const float* bo    = (const float*)d_in[12];
    const float* gamma = (const float*)d_in[13];
    const float* beta  = (const float*)d_in[14];
    float* out = (float*)d_out;

    k_gc<<<520, 192>>>(x);
    launch_pdl(k_gemm1, dim3(120), dim3(192), Wv, W1);
    launch_pdl(k_gemm2, dim3(48),  dim3(192), W2, b1);
    launch_pdl(k_gemm3, dim3(96),  dim3(192), Wo, bv, b2);
    launch_pdl(k_ln,    dim3(512), dim3(256), x, bo, gamma, beta, out);
}